// round 10
// baseline (speedup 1.0000x reference)
#include <cuda_runtime.h>
#include <math.h>
#include <stdint.h>

// Problem constants
#define MTOT   8192      // B*T
#define CEMB   768
#define C3     2304
#define NHEAD  12
#define DH     64
#define TSEQ   2048
#define BBATCH 4

typedef unsigned long long u64;

// Scratch (device globals: allocation-free per harness rules)
__device__ float g_qkv[(size_t)MTOT * C3];   // [8192, 2304]
__device__ float g_y  [(size_t)MTOT * CEMB]; // [8192, 768]

// ---------------------------------------------------------------------------
// f32x2 packed-math helpers (Blackwell sm_100+)
// ---------------------------------------------------------------------------
__device__ __forceinline__ void ffma2(u64& d, u64 a, u64 b) {
    asm("fma.rn.f32x2 %0, %1, %2, %0;" : "+l"(d) : "l"(a), "l"(b));
}
__device__ __forceinline__ u64 dup2(float x) {
    u64 r; unsigned xi = __float_as_uint(x);
    asm("mov.b64 %0, {%1, %1};" : "=l"(r) : "r"(xi));
    return r;
}
__device__ __forceinline__ void unpack2(u64 v, float& lo, float& hi) {
    unsigned a, b;
    asm("mov.b64 {%0, %1}, %2;" : "=r"(a), "=r"(b) : "l"(v));
    lo = __uint_as_float(a); hi = __uint_as_float(b);
}
__device__ __forceinline__ void mul2(u64& d, u64 a) {
    asm("mul.rn.f32x2 %0, %0, %1;" : "+l"(d) : "l"(a));
}
__device__ __forceinline__ float fast_exp2(float x) {
    float y;
    asm("ex2.approx.ftz.f32 %0, %1;" : "=f"(y) : "f"(x));
    return y;
}

// ---------------------------------------------------------------------------
// SGEMM: C[M,N] = A[M,K] @ B[K,N], row-major. Block 128(M)x256(N), BK=16,
// 256 threads, 8x16 micro-tile computed as 8x8 FFMA2 (f32x2 packed pairs
// along N). A stored DUPLICATED in smem so the broadcast operand is a
// natural (a,a) pair. Double-buffered smem, register-staged prefetch.
// Requires M%128==0, N%256==0, K%16==0. Dynamic smem = 64 KB.
// ---------------------------------------------------------------------------
#define BM 128
#define BN 256
#define BK 16

__global__ __launch_bounds__(256, 1)
void sgemm_fast(const float* __restrict__ A, const float* __restrict__ B,
                float* __restrict__ C, int N, int K) {
    extern __shared__ float smg[];
    float* As2 = smg;                       // [2][BK][2*BM]  (dup: As2[k][2m]=As2[k][2m+1]=A)
    float* Bs  = smg + 2 * BK * 2 * BM;     // [2][BK][BN]
#define AS2(b,k,m2) As2[((b) * BK + (k)) * (2*BM) + (m2)]
#define BS(b,k,n)   Bs [((b) * BK + (k)) * BN + (n)]

    const int tid  = threadIdx.x;
    const int ty   = tid >> 4;        // 0..15 -> rows ty*8..+7
    const int tx   = tid & 15;        // cols 4*tx + {0,64,128,192}
    const int brow = blockIdx.y;
    const int bcol = blockIdx.x;

    const float* Ab = A + (size_t)brow * BM * K;
    const float* Bb = B + (size_t)bcol * BN;

    // A loader: row ar (0..127), cols ac..ac+7  (two float4)
    const int ar = tid >> 1;
    const int ac = (tid & 1) * 8;
    // B loader: 4 rows rb..rb+3, one float4 at col cb per row
    const int rb = (tid >> 6) * 4;
    const int cb = (tid & 63) * 4;

    float4 pa0, pa1, pb[4];

    // prefetch kt = 0
    pa0 = *(const float4*)(Ab + (size_t)ar * K + ac);
    pa1 = *(const float4*)(Ab + (size_t)ar * K + ac + 4);
#pragma unroll
    for (int i = 0; i < 4; i++)
        pb[i] = *(const float4*)(Bb + (size_t)(rb + i) * N + cb);

    // store buffer 0 (A duplicated)
    {
        float av[8] = {pa0.x, pa0.y, pa0.z, pa0.w, pa1.x, pa1.y, pa1.z, pa1.w};
#pragma unroll
        for (int j = 0; j < 8; j++)
            *(float2*)&AS2(0, ac + j, 2 * ar) = make_float2(av[j], av[j]);
    }
#pragma unroll
    for (int i = 0; i < 4; i++)
        *(float4*)&BS(0, rb + i, cb) = pb[i];
    __syncthreads();

    u64 acc2[8][8];
#pragma unroll
    for (int i = 0; i < 8; i++)
#pragma unroll
        for (int j = 0; j < 8; j++) acc2[i][j] = 0ull;

    const int nk = K / BK;
    for (int kt = 0; kt < nk; kt++) {
        const int cur = kt & 1;
        const int nxt = cur ^ 1;

        if (kt + 1 < nk) {
            const float* Ak = Ab + (kt + 1) * BK;
            pa0 = *(const float4*)(Ak + (size_t)ar * K + ac);
            pa1 = *(const float4*)(Ak + (size_t)ar * K + ac + 4);
            const float* Bk = Bb + (size_t)(kt + 1) * BK * N;
#pragma unroll
            for (int i = 0; i < 4; i++)
                pb[i] = *(const float4*)(Bk + (size_t)(rb + i) * N + cb);
        }

#pragma unroll
        for (int k = 0; k < BK; k++) {
            u64 ra2[8], rv2[8];
#pragma unroll
            for (int h = 0; h < 4; h++) {
                ulonglong2 t = *(const ulonglong2*)&AS2(cur, k, ty * 16 + 4 * h);
                ra2[2 * h] = t.x; ra2[2 * h + 1] = t.y;
            }
#pragma unroll
            for (int c = 0; c < 4; c++) {
                ulonglong2 t = *(const ulonglong2*)&BS(cur, k, tx * 4 + c * 64);
                rv2[2 * c] = t.x; rv2[2 * c + 1] = t.y;
            }
#pragma unroll
            for (int i = 0; i < 8; i++)
#pragma unroll
                for (int j = 0; j < 8; j++)
                    ffma2(acc2[i][j], ra2[i], rv2[j]);
        }

        if (kt + 1 < nk) {
            float av[8] = {pa0.x, pa0.y, pa0.z, pa0.w, pa1.x, pa1.y, pa1.z, pa1.w};
#pragma unroll
            for (int j = 0; j < 8; j++)
                *(float2*)&AS2(nxt, ac + j, 2 * ar) = make_float2(av[j], av[j]);
#pragma unroll
            for (int i = 0; i < 4; i++)
                *(float4*)&BS(nxt, rb + i, cb) = pb[i];
            __syncthreads();
        }
    }

    // epilogue
#pragma unroll
    for (int i = 0; i < 8; i++) {
        float* Cr = C + (size_t)(brow * BM + ty * 8 + i) * N + (size_t)bcol * BN;
#pragma unroll
        for (int c = 0; c < 4; c++) {
            float a0, a1, a2, a3;
            unpack2(acc2[i][2 * c],     a0, a1);
            unpack2(acc2[i][2 * c + 1], a2, a3);
            *(float4*)(Cr + c * 64 + tx * 4) = make_float4(a0, a1, a2, a3);
        }
    }
#undef AS2
#undef BS
}

// ---------------------------------------------------------------------------
// Flash attention (fp32 accuracy via packed f32x2 FMA), 128q x 128k tiles.
// Grid: (T/128, NHEAD, B). Block: 256 threads.
// Thread (tq,tk)=(tid>>4, tid&15):
//   S micro-tile 8q x 8k as 8x4 FFMA2 (pairs over k)
//   PV micro-tile 8q x 4d as 8x2 FFMA2 (pairs over d, p dup'd)
// smem (192 KB): Qt2[64][256] (d-major, q-duplicated), Kt[64][128] (d-major),
// Vs[128][64], Pq[128][128] (query-major).
// Q pre-scaled by sqrt(Dh)*log2(e) so softmax uses raw ex2.approx.
// ---------------------------------------------------------------------------
__global__ __launch_bounds__(256, 1)
void flash_attn2(const float* __restrict__ qkv, float* __restrict__ y) {
    extern __shared__ float sm[];
    float* Qt2 = sm;                  // [64][256]
    float* Kt  = Qt2 + 64 * 256;      // [64][128]
    float* Vs  = Kt  + 64 * 128;      // [128][64]
    float* Pq  = Vs  + 128 * 64;      // [128][128]

    const int tid = threadIdx.x;
    const int tq  = tid >> 4;       // 0..15
    const int tk  = tid & 15;       // 0..15

    const int qtile = blockIdx.x;
    const int h     = blockIdx.y;
    const int b     = blockIdx.z;

    const size_t rowbase = (size_t)b * TSEQ;
    const int qbase = qtile * 128;
    const int qcol = h * DH;
    const int kcol = CEMB + h * DH;
    const int vcol = 2 * CEMB + h * DH;

    // loader mapping (Q/K transpose): row la_r, cols la_c..la_c+31
    const int la_r = tid >> 1;           // 0..127
    const int la_c = (tid & 1) * 32;     // 0 or 32
    // loader mapping (V): rows 16*i + vg, col float4 at 4*vt
    const int vg = tid >> 4;
    const int vt = tid & 15;

    const int q_lo = 4 * tq;
    const int q_hi = 64 + 4 * tq;

    // ---- Load Q tile -> Qt2 (d-major, duplicated), scaled by 8*log2(e) ----
    {
        const float QS = 8.0f * 1.4426950408889634f;
        const float* qb = qkv + (rowbase + qbase + la_r) * (size_t)C3 + qcol + la_c;
#pragma unroll
        for (int j = 0; j < 8; j++) {
            float4 v = *(const float4*)(qb + 4 * j);
            float vv[4] = {v.x * QS, v.y * QS, v.z * QS, v.w * QS};
#pragma unroll
            for (int e = 0; e < 4; e++)
                *(float2*)&Qt2[(la_c + 4 * j + e) * 256 + 2 * la_r] =
                    make_float2(vv[e], vv[e]);
        }
    }

    // ---- Prefetch K tile 0 into registers ----
    float4 kp[8];
    {
        const float* kb = qkv + (rowbase + la_r) * (size_t)C3 + kcol + la_c;
#pragma unroll
        for (int j = 0; j < 8; j++) kp[j] = *(const float4*)(kb + 4 * j);
    }

    float m[8], l[8];
    u64 acc2[8][2];
#pragma unroll
    for (int i = 0; i < 8; i++) {
        m[i] = -3.0e38f;
        l[i] = 0.0f;
        acc2[i][0] = 0ull;
        acc2[i][1] = 0ull;
    }

    for (int t = 0; t < TSEQ / 128; t++) {
        __syncthreads();   // Kt/Vs/Pq free (prev tile fully consumed)

        // ---- STS K from prefetch regs (transposed, d-major) ----
#pragma unroll
        for (int j = 0; j < 8; j++) {
            Kt[(la_c + 4 * j + 0) * 128 + la_r] = kp[j].x;
            Kt[(la_c + 4 * j + 1) * 128 + la_r] = kp[j].y;
            Kt[(la_c + 4 * j + 2) * 128 + la_r] = kp[j].z;
            Kt[(la_c + 4 * j + 3) * 128 + la_r] = kp[j].w;
        }
        __syncthreads();

        // ---- Issue next-K prefetch + this tile's V load ----
        if (t + 1 < TSEQ / 128) {
            const float* kb = qkv + (rowbase + (size_t)(t + 1) * 128 + la_r) * C3 + kcol + la_c;
#pragma unroll
            for (int j = 0; j < 8; j++) kp[j] = *(const float4*)(kb + 4 * j);
        }
        float4 vp[8];
        {
            const float* vb = qkv + (rowbase + (size_t)t * 128) * C3 + vcol;
#pragma unroll
            for (int i = 0; i < 8; i++)
                vp[i] = *(const float4*)(vb + (size_t)(16 * i + vg) * C3 + 4 * vt);
        }

        // ---- S = Q @ K^T  (8q x 8k per thread; f32x2 pairs over k) ----
        u64 s2[8][4];
#pragma unroll
        for (int i = 0; i < 8; i++)
#pragma unroll
            for (int j = 0; j < 4; j++) s2[i][j] = 0ull;

#pragma unroll 2
        for (int d = 0; d < 64; d++) {
            ulonglong2 qa = *(const ulonglong2*)&Qt2[d * 256 + 2 * q_lo];
            ulonglong2 qb = *(const ulonglong2*)&Qt2[d * 256 + 2 * q_lo + 4];
            ulonglong2 qc = *(const ulonglong2*)&Qt2[d * 256 + 2 * q_hi];
            ulonglong2 qd = *(const ulonglong2*)&Qt2[d * 256 + 2 * q_hi + 4];
            ulonglong2 ka = *(const ulonglong2*)&Kt[d * 128 + 4 * tk];
            ulonglong2 kb = *(const ulonglong2*)&Kt[d * 128 + 64 + 4 * tk];
            u64 rq[8] = {qa.x, qa.y, qb.x, qb.y, qc.x, qc.y, qd.x, qd.y};
            u64 rk[4] = {ka.x, ka.y, kb.x, kb.y};
#pragma unroll
            for (int i = 0; i < 8; i++)
#pragma unroll
                for (int j = 0; j < 4; j++)
                    ffma2(s2[i][j], rq[i], rk[j]);
        }

        // ---- Online softmax (base-2 domain; row stats over 16-lane group) ----
        float s[8][8];
#pragma unroll
        for (int i = 0; i < 8; i++)
#pragma unroll
            for (int j = 0; j < 4; j++)
                unpack2(s2[i][j], s[i][2 * j], s[i][2 * j + 1]);

#pragma unroll
        for (int i = 0; i < 8; i++) {
            float mx = s[i][0];
#pragma unroll
            for (int j = 1; j < 8; j++) mx = fmaxf(mx, s[i][j]);
            mx = fmaxf(mx, __shfl_xor_sync(0xffffffffu, mx, 1));
            mx = fmaxf(mx, __shfl_xor_sync(0xffffffffu, mx, 2));
            mx = fmaxf(mx, __shfl_xor_sync(0xffffffffu, mx, 4));
            mx = fmaxf(mx, __shfl_xor_sync(0xffffffffu, mx, 8));
            float mnew = fmaxf(m[i], mx);
            float alpha = fast_exp2(m[i] - mnew);
            float lsum = 0.0f;
#pragma unroll
            for (int j = 0; j < 8; j++) {
                float p = fast_exp2(s[i][j] - mnew);
                s[i][j] = p;
                lsum += p;
            }
            lsum += __shfl_xor_sync(0xffffffffu, lsum, 1);
            lsum += __shfl_xor_sync(0xffffffffu, lsum, 2);
            lsum += __shfl_xor_sync(0xffffffffu, lsum, 4);
            lsum += __shfl_xor_sync(0xffffffffu, lsum, 8);
            l[i] = l[i] * alpha + lsum;
            m[i] = mnew;
            u64 ad = dup2(alpha);
            mul2(acc2[i][0], ad);
            mul2(acc2[i][1], ad);
        }

        // ---- Store P (query-major): conflict-free float4 STS ----
#pragma unroll
        for (int i = 0; i < 8; i++) {
            const int qi = (i < 4) ? (q_lo + i) : (q_hi + i - 4);
            *(float4*)&Pq[qi * 128 + 4 * tk] =
                make_float4(s[i][0], s[i][1], s[i][2], s[i][3]);
            *(float4*)&Pq[qi * 128 + 64 + 4 * tk] =
                make_float4(s[i][4], s[i][5], s[i][6], s[i][7]);
        }
        // ---- STS V ----
#pragma unroll
        for (int i = 0; i < 8; i++)
            *(float4*)&Vs[(16 * i + vg) * 64 + 4 * vt] = vp[i];
        __syncthreads();

        // ---- acc += P @ V  (8q x 4d per thread; f32x2 pairs over d) ----
#pragma unroll 2
        for (int s0 = 0; s0 < 128; s0 += 4) {
            float4 p[8];
#pragma unroll
            for (int i = 0; i < 8; i++) {
                const int qi = (i < 4) ? (q_lo + i) : (q_hi + i - 4);
                p[i] = *(const float4*)&Pq[qi * 128 + s0];
            }
#pragma unroll
            for (int ss = 0; ss < 4; ss++) {
                ulonglong2 v2 = *(const ulonglong2*)&Vs[(s0 + ss) * 64 + 4 * tk];
#pragma unroll
                for (int i = 0; i < 8; i++) {
                    float pi = (ss == 0) ? p[i].x : (ss == 1) ? p[i].y
                             : (ss == 2) ? p[i].z : p[i].w;
                    u64 pd = dup2(pi);
                    ffma2(acc2[i][0], pd, v2.x);
                    ffma2(acc2[i][1], pd, v2.y);
                }
            }
        }
    }

    // ---- Epilogue: y[b*T + q, h*64 + 4tk..] = acc / l ----
#pragma unroll
    for (int i = 0; i < 8; i++) {
        const int qi = (i < 4) ? (q_lo + i) : (q_hi + i - 4);
        const float inv = 1.0f / l[i];
        float a0, a1, a2, a3;
        unpack2(acc2[i][0], a0, a1);
        unpack2(acc2[i][1], a2, a3);
        float* yr = y + (rowbase + qbase + qi) * (size_t)CEMB + h * DH + 4 * tk;
        *(float4*)yr = make_float4(a0 * inv, a1 * inv, a2 * inv, a3 * inv);
    }
}

// ---------------------------------------------------------------------------
// Launch
// ---------------------------------------------------------------------------
extern "C" void kernel_launch(void* const* d_in, const int* in_sizes, int n_in,
                              void* d_out, int out_size) {
    const float* x     = (const float*)d_in[0];   // [4,2048,768]
    const float* Wqkv  = (const float*)d_in[1];   // [768,2304]
    const float* Wproj = (const float*)d_in[2];   // [768,768]
    float* out = (float*)d_out;                   // [4,2048,768]

    float *qkv = nullptr, *yb = nullptr;
    cudaGetSymbolAddress((void**)&qkv, g_qkv);
    cudaGetSymbolAddress((void**)&yb,  g_y);

    const int gemm_smem = (2 * BK * 2 * BM + 2 * BK * BN) * (int)sizeof(float); // 65536
    cudaFuncSetAttribute(sgemm_fast,
                         cudaFuncAttributeMaxDynamicSharedMemorySize, gemm_smem);

    // 1) qkv = x @ W_qkv : [8192,768] x [768,2304]
    sgemm_fast<<<dim3(C3 / BN, MTOT / BM), 256, gemm_smem>>>(x, Wqkv, qkv, C3, CEMB);

    // 2) flash attention -> g_y
    const int fa_smem = (64 * 256 + 64 * 128 + 128 * 64 + 128 * 128) * (int)sizeof(float); // 196608
    cudaFuncSetAttribute(flash_attn2,
                         cudaFuncAttributeMaxDynamicSharedMemorySize, fa_smem);
    flash_attn2<<<dim3(TSEQ / 128, NHEAD, BBATCH), 256, fa_smem>>>(qkv, yb);

    // 3) out = y @ W_proj : [8192,768] x [768,768]
    sgemm_fast<<<dim3(CEMB / BN, MTOT / BM), 256, gemm_smem>>>(yb, Wproj, out, CEMB, CEMB);
}

// round 11
// speedup vs baseline: 1.6102x; 1.6102x over previous
#include <cuda_runtime.h>
#include <math.h>
#include <stdint.h>

// Problem constants
#define MTOT   8192      // B*T
#define CEMB   768
#define C3     2304
#define NHEAD  12
#define DH     64
#define TSEQ   2048
#define BBATCH 4

typedef unsigned long long u64;

// Scratch (device globals: allocation-free per harness rules)
__device__ float g_qkv[(size_t)MTOT * C3];   // [8192, 2304]
__device__ float g_y  [(size_t)MTOT * CEMB]; // [8192, 768]

// ---------------------------------------------------------------------------
// f32x2 packed-math helpers (Blackwell sm_100+)
// ---------------------------------------------------------------------------
__device__ __forceinline__ void ffma2(u64& d, u64 a, u64 b) {
    asm("fma.rn.f32x2 %0, %1, %2, %0;" : "+l"(d) : "l"(a), "l"(b));
}
__device__ __forceinline__ u64 dup2(float x) {
    u64 r; unsigned xi = __float_as_uint(x);
    asm("mov.b64 %0, {%1, %1};" : "=l"(r) : "r"(xi));
    return r;
}
__device__ __forceinline__ void unpack2(u64 v, float& lo, float& hi) {
    unsigned a, b;
    asm("mov.b64 {%0, %1}, %2;" : "=r"(a), "=r"(b) : "l"(v));
    lo = __uint_as_float(a); hi = __uint_as_float(b);
}
__device__ __forceinline__ void mul2(u64& d, u64 a) {
    asm("mul.rn.f32x2 %0, %0, %1;" : "+l"(d) : "l"(a));
}
__device__ __forceinline__ float fast_exp2(float x) {
    float y;
    asm("ex2.approx.ftz.f32 %0, %1;" : "=f"(y) : "f"(x));
    return y;
}

// ---------------------------------------------------------------------------
// SGEMM: C[M,N] = A[M,K] @ B[K,N], row-major. Block 128(M)x256(N), BK=16,
// 256 threads, 8x16 micro-tile computed as 8x8 FFMA2 (f32x2 packed pairs
// along N). A stored DUPLICATED in smem so the broadcast operand is a
// natural (a,a) pair. Double-buffered smem, register-staged prefetch.
// Requires M%128==0, N%256==0, K%16==0. Dynamic smem = 64 KB.
// ---------------------------------------------------------------------------
#define BM 128
#define BN 256
#define BK 16

__global__ __launch_bounds__(256, 1)
void sgemm_fast(const float* __restrict__ A, const float* __restrict__ B,
                float* __restrict__ C, int N, int K) {
    extern __shared__ float smg[];
    float* As2 = smg;                       // [2][BK][2*BM]  (dup: As2[k][2m]=As2[k][2m+1]=A)
    float* Bs  = smg + 2 * BK * 2 * BM;     // [2][BK][BN]
#define AS2(b,k,m2) As2[((b) * BK + (k)) * (2*BM) + (m2)]
#define BS(b,k,n)   Bs [((b) * BK + (k)) * BN + (n)]

    const int tid  = threadIdx.x;
    const int ty   = tid >> 4;        // 0..15 -> rows ty*8..+7
    const int tx   = tid & 15;        // cols 4*tx + {0,64,128,192}
    const int brow = blockIdx.y;
    const int bcol = blockIdx.x;

    const float* Ab = A + (size_t)brow * BM * K;
    const float* Bb = B + (size_t)bcol * BN;

    // A loader: row ar (0..127), cols ac..ac+7  (two float4)
    const int ar = tid >> 1;
    const int ac = (tid & 1) * 8;
    // B loader: 4 rows rb..rb+3, one float4 at col cb per row
    const int rb = (tid >> 6) * 4;
    const int cb = (tid & 63) * 4;

    float4 pa0, pa1, pb[4];

    // prefetch kt = 0
    pa0 = *(const float4*)(Ab + (size_t)ar * K + ac);
    pa1 = *(const float4*)(Ab + (size_t)ar * K + ac + 4);
#pragma unroll
    for (int i = 0; i < 4; i++)
        pb[i] = *(const float4*)(Bb + (size_t)(rb + i) * N + cb);

    // store buffer 0 (A duplicated)
    {
        float av[8] = {pa0.x, pa0.y, pa0.z, pa0.w, pa1.x, pa1.y, pa1.z, pa1.w};
#pragma unroll
        for (int j = 0; j < 8; j++)
            *(float2*)&AS2(0, ac + j, 2 * ar) = make_float2(av[j], av[j]);
    }
#pragma unroll
    for (int i = 0; i < 4; i++)
        *(float4*)&BS(0, rb + i, cb) = pb[i];
    __syncthreads();

    u64 acc2[8][8];
#pragma unroll
    for (int i = 0; i < 8; i++)
#pragma unroll
        for (int j = 0; j < 8; j++) acc2[i][j] = 0ull;

    const int nk = K / BK;
    for (int kt = 0; kt < nk; kt++) {
        const int cur = kt & 1;
        const int nxt = cur ^ 1;

        if (kt + 1 < nk) {
            const float* Ak = Ab + (kt + 1) * BK;
            pa0 = *(const float4*)(Ak + (size_t)ar * K + ac);
            pa1 = *(const float4*)(Ak + (size_t)ar * K + ac + 4);
            const float* Bk = Bb + (size_t)(kt + 1) * BK * N;
#pragma unroll
            for (int i = 0; i < 4; i++)
                pb[i] = *(const float4*)(Bk + (size_t)(rb + i) * N + cb);
        }

#pragma unroll
        for (int k = 0; k < BK; k++) {
            u64 ra2[8], rv2[8];
#pragma unroll
            for (int h = 0; h < 4; h++) {
                ulonglong2 t = *(const ulonglong2*)&AS2(cur, k, ty * 16 + 4 * h);
                ra2[2 * h] = t.x; ra2[2 * h + 1] = t.y;
            }
#pragma unroll
            for (int c = 0; c < 4; c++) {
                ulonglong2 t = *(const ulonglong2*)&BS(cur, k, tx * 4 + c * 64);
                rv2[2 * c] = t.x; rv2[2 * c + 1] = t.y;
            }
#pragma unroll
            for (int i = 0; i < 8; i++)
#pragma unroll
                for (int j = 0; j < 8; j++)
                    ffma2(acc2[i][j], ra2[i], rv2[j]);
        }

        if (kt + 1 < nk) {
            float av[8] = {pa0.x, pa0.y, pa0.z, pa0.w, pa1.x, pa1.y, pa1.z, pa1.w};
#pragma unroll
            for (int j = 0; j < 8; j++)
                *(float2*)&AS2(nxt, ac + j, 2 * ar) = make_float2(av[j], av[j]);
#pragma unroll
            for (int i = 0; i < 4; i++)
                *(float4*)&BS(nxt, rb + i, cb) = pb[i];
            __syncthreads();
        }
    }

    // epilogue
#pragma unroll
    for (int i = 0; i < 8; i++) {
        float* Cr = C + (size_t)(brow * BM + ty * 8 + i) * N + (size_t)bcol * BN;
#pragma unroll
        for (int c = 0; c < 4; c++) {
            float a0, a1, a2, a3;
            unpack2(acc2[i][2 * c],     a0, a1);
            unpack2(acc2[i][2 * c + 1], a2, a3);
            *(float4*)(Cr + c * 64 + tx * 4) = make_float4(a0, a1, a2, a3);
        }
    }
#undef AS2
#undef BS
}

// ---------------------------------------------------------------------------
// Flash attention (fp32 accuracy via packed f32x2 FMA), 128q x 128k tiles.
// Grid: (T/128, NHEAD, B). Block: 256 threads.
// Thread (tq,tk)=(tid>>4, tid&15):
//   S micro-tile 8q x 8k as 8x4 FFMA2 (pairs over k)
//   PV micro-tile 8q x 4d as 8x2 FFMA2 (pairs over d, p dup'd)
// smem (192 KB): Qt2[64][256] (d-major, q-duplicated), Kt[64][128] (d-major),
// Vs[128][64], Pq[128][128] (query-major).
// Q pre-scaled by sqrt(Dh)*log2(e) so softmax uses raw ex2.approx.
// ---------------------------------------------------------------------------
__global__ __launch_bounds__(256, 1)
void flash_attn2(const float* __restrict__ qkv, float* __restrict__ y) {
    extern __shared__ float sm[];
    float* Qt2 = sm;                  // [64][256]
    float* Kt  = Qt2 + 64 * 256;      // [64][128]
    float* Vs  = Kt  + 64 * 128;      // [128][64]
    float* Pq  = Vs  + 128 * 64;      // [128][128]

    const int tid = threadIdx.x;
    const int tq  = tid >> 4;       // 0..15
    const int tk  = tid & 15;       // 0..15

    const int qtile = blockIdx.x;
    const int h     = blockIdx.y;
    const int b     = blockIdx.z;

    const size_t rowbase = (size_t)b * TSEQ;
    const int qbase = qtile * 128;
    const int qcol = h * DH;
    const int kcol = CEMB + h * DH;
    const int vcol = 2 * CEMB + h * DH;

    // loader mapping (Q/K transpose): row la_r, cols la_c..la_c+31
    const int la_r = tid >> 1;           // 0..127
    const int la_c = (tid & 1) * 32;     // 0 or 32
    // loader mapping (V): rows 16*i + vg, col float4 at 4*vt
    const int vg = tid >> 4;
    const int vt = tid & 15;

    const int q_lo = 4 * tq;
    const int q_hi = 64 + 4 * tq;

    // ---- Load Q tile -> Qt2 (d-major, duplicated), scaled by 8*log2(e) ----
    {
        const float QS = 8.0f * 1.4426950408889634f;
        const float* qb = qkv + (rowbase + qbase + la_r) * (size_t)C3 + qcol + la_c;
#pragma unroll
        for (int j = 0; j < 8; j++) {
            float4 v = *(const float4*)(qb + 4 * j);
            float vv[4] = {v.x * QS, v.y * QS, v.z * QS, v.w * QS};
#pragma unroll
            for (int e = 0; e < 4; e++)
                *(float2*)&Qt2[(la_c + 4 * j + e) * 256 + 2 * la_r] =
                    make_float2(vv[e], vv[e]);
        }
    }

    // ---- Prefetch K tile 0 into registers ----
    float4 kp[8];
    {
        const float* kb = qkv + (rowbase + la_r) * (size_t)C3 + kcol + la_c;
#pragma unroll
        for (int j = 0; j < 8; j++) kp[j] = *(const float4*)(kb + 4 * j);
    }

    float m[8], l[8];
    u64 acc2[8][2];
#pragma unroll
    for (int i = 0; i < 8; i++) {
        m[i] = -3.0e38f;
        l[i] = 0.0f;
        acc2[i][0] = 0ull;
        acc2[i][1] = 0ull;
    }

    for (int t = 0; t < TSEQ / 128; t++) {
        __syncthreads();   // Kt/Vs/Pq free (prev tile fully consumed)

        // ---- STS K from prefetch regs (transposed, d-major) ----
#pragma unroll
        for (int j = 0; j < 8; j++) {
            Kt[(la_c + 4 * j + 0) * 128 + la_r] = kp[j].x;
            Kt[(la_c + 4 * j + 1) * 128 + la_r] = kp[j].y;
            Kt[(la_c + 4 * j + 2) * 128 + la_r] = kp[j].z;
            Kt[(la_c + 4 * j + 3) * 128 + la_r] = kp[j].w;
        }
        __syncthreads();

        // ---- Issue next-K prefetch + this tile's V load ----
        if (t + 1 < TSEQ / 128) {
            const float* kb = qkv + (rowbase + (size_t)(t + 1) * 128 + la_r) * C3 + kcol + la_c;
#pragma unroll
            for (int j = 0; j < 8; j++) kp[j] = *(const float4*)(kb + 4 * j);
        }
        float4 vp[8];
        {
            const float* vb = qkv + (rowbase + (size_t)t * 128) * C3 + vcol;
#pragma unroll
            for (int i = 0; i < 8; i++)
                vp[i] = *(const float4*)(vb + (size_t)(16 * i + vg) * C3 + 4 * vt);
        }

        // ---- S = Q @ K^T  (8q x 8k per thread; f32x2 pairs over k) ----
        u64 s2[8][4];
#pragma unroll
        for (int i = 0; i < 8; i++)
#pragma unroll
            for (int j = 0; j < 4; j++) s2[i][j] = 0ull;

#pragma unroll 2
        for (int d = 0; d < 64; d++) {
            ulonglong2 qa = *(const ulonglong2*)&Qt2[d * 256 + 2 * q_lo];
            ulonglong2 qb = *(const ulonglong2*)&Qt2[d * 256 + 2 * q_lo + 4];
            ulonglong2 qc = *(const ulonglong2*)&Qt2[d * 256 + 2 * q_hi];
            ulonglong2 qd = *(const ulonglong2*)&Qt2[d * 256 + 2 * q_hi + 4];
            ulonglong2 ka = *(const ulonglong2*)&Kt[d * 128 + 4 * tk];
            ulonglong2 kb = *(const ulonglong2*)&Kt[d * 128 + 64 + 4 * tk];
            u64 rq[8] = {qa.x, qa.y, qb.x, qb.y, qc.x, qc.y, qd.x, qd.y};
            u64 rk[4] = {ka.x, ka.y, kb.x, kb.y};
#pragma unroll
            for (int i = 0; i < 8; i++)
#pragma unroll
                for (int j = 0; j < 4; j++)
                    ffma2(s2[i][j], rq[i], rk[j]);
        }

        // ---- Online softmax (base-2 domain; row stats over 16-lane group) ----
        float s[8][8];
#pragma unroll
        for (int i = 0; i < 8; i++)
#pragma unroll
            for (int j = 0; j < 4; j++)
                unpack2(s2[i][j], s[i][2 * j], s[i][2 * j + 1]);

#pragma unroll
        for (int i = 0; i < 8; i++) {
            float mx = s[i][0];
#pragma unroll
            for (int j = 1; j < 8; j++) mx = fmaxf(mx, s[i][j]);
            mx = fmaxf(mx, __shfl_xor_sync(0xffffffffu, mx, 1));
            mx = fmaxf(mx, __shfl_xor_sync(0xffffffffu, mx, 2));
            mx = fmaxf(mx, __shfl_xor_sync(0xffffffffu, mx, 4));
            mx = fmaxf(mx, __shfl_xor_sync(0xffffffffu, mx, 8));
            float mnew = fmaxf(m[i], mx);
            float alpha = fast_exp2(m[i] - mnew);
            float lsum = 0.0f;
#pragma unroll
            for (int j = 0; j < 8; j++) {
                float p = fast_exp2(s[i][j] - mnew);
                s[i][j] = p;
                lsum += p;
            }
            lsum += __shfl_xor_sync(0xffffffffu, lsum, 1);
            lsum += __shfl_xor_sync(0xffffffffu, lsum, 2);
            lsum += __shfl_xor_sync(0xffffffffu, lsum, 4);
            lsum += __shfl_xor_sync(0xffffffffu, lsum, 8);
            l[i] = l[i] * alpha + lsum;
            m[i] = mnew;
            u64 ad = dup2(alpha);
            mul2(acc2[i][0], ad);
            mul2(acc2[i][1], ad);
        }

        // ---- Store P (query-major): conflict-free float4 STS ----
#pragma unroll
        for (int i = 0; i < 8; i++) {
            const int qi = (i < 4) ? (q_lo + i) : (q_hi + i - 4);
            *(float4*)&Pq[qi * 128 + 4 * tk] =
                make_float4(s[i][0], s[i][1], s[i][2], s[i][3]);
            *(float4*)&Pq[qi * 128 + 64 + 4 * tk] =
                make_float4(s[i][4], s[i][5], s[i][6], s[i][7]);
        }
        // ---- STS V ----
#pragma unroll
        for (int i = 0; i < 8; i++)
            *(float4*)&Vs[(16 * i + vg) * 64 + 4 * vt] = vp[i];
        __syncthreads();

        // ---- acc += P @ V  (8q x 4d per thread; f32x2 pairs over d) ----
#pragma unroll 2
        for (int s0 = 0; s0 < 128; s0 += 4) {
            float4 p[8];
#pragma unroll
            for (int i = 0; i < 8; i++) {
                const int qi = (i < 4) ? (q_lo + i) : (q_hi + i - 4);
                p[i] = *(const float4*)&Pq[qi * 128 + s0];
            }
#pragma unroll
            for (int ss = 0; ss < 4; ss++) {
                ulonglong2 v2 = *(const ulonglong2*)&Vs[(s0 + ss) * 64 + 4 * tk];
#pragma unroll
                for (int i = 0; i < 8; i++) {
                    float pi = (ss == 0) ? p[i].x : (ss == 1) ? p[i].y
                             : (ss == 2) ? p[i].z : p[i].w;
                    u64 pd = dup2(pi);
                    ffma2(acc2[i][0], pd, v2.x);
                    ffma2(acc2[i][1], pd, v2.y);
                }
            }
        }
    }

    // ---- Epilogue: y[b*T + q, h*64 + 4tk..] = acc / l ----
#pragma unroll
    for (int i = 0; i < 8; i++) {
        const int qi = (i < 4) ? (q_lo + i) : (q_hi + i - 4);
        const float inv = 1.0f / l[i];
        float a0, a1, a2, a3;
        unpack2(acc2[i][0], a0, a1);
        unpack2(acc2[i][1], a2, a3);
        float* yr = y + (rowbase + qbase + qi) * (size_t)CEMB + h * DH + 4 * tk;
        *(float4*)yr = make_float4(a0 * inv, a1 * inv, a2 * inv, a3 * inv);
    }
}

// ---------------------------------------------------------------------------
// Launch
// ---------------------------------------------------------------------------
extern "C" void kernel_launch(void* const* d_in, const int* in_sizes, int n_in,
                              void* d_out, int out_size) {
    const float* x     = (const float*)d_in[0];   // [4,2048,768]
    const float* Wqkv  = (const float*)d_in[1];   // [768,2304]
    const float* Wproj = (const float*)d_in[2];   // [768,768]
    float* out = (float*)d_out;                   // [4,2048,768]

    float *qkv = nullptr, *yb = nullptr;
    cudaGetSymbolAddress((void**)&qkv, g_qkv);
    cudaGetSymbolAddress((void**)&yb,  g_y);

    const int gemm_smem = (2 * BK * 2 * BM + 2 * BK * BN) * (int)sizeof(float); // 65536
    cudaFuncSetAttribute(sgemm_fast,
                         cudaFuncAttributeMaxDynamicSharedMemorySize, gemm_smem);

    // 1) qkv = x @ W_qkv : [8192,768] x [768,2304]
    sgemm_fast<<<dim3(C3 / BN, MTOT / BM), 256, gemm_smem>>>(x, Wqkv, qkv, C3, CEMB);

    // 2) flash attention -> g_y
    const int fa_smem = (64 * 256 + 64 * 128 + 128 * 64 + 128 * 128) * (int)sizeof(float); // 196608
    cudaFuncSetAttribute(flash_attn2,
                         cudaFuncAttributeMaxDynamicSharedMemorySize, fa_smem);
    flash_attn2<<<dim3(TSEQ / 128, NHEAD, BBATCH), 256, fa_smem>>>(qkv, yb);

    // 3) out = y @ W_proj : [8192,768] x [768,768]
    sgemm_fast<<<dim3(CEMB / BN, MTOT / BM), 256, gemm_smem>>>(yb, Wproj, out, CEMB, CEMB);
}